// round 1
// baseline (speedup 1.0000x reference)
#include <cuda_runtime.h>

#define NSIZE 20000
#define NEDGE 600000
#define BATCH 128
#define NITER 120
#define LEAK  0.01f

// Scratch: __device__ globals (no allocation allowed).
__device__ float g_state0[NSIZE * BATCH];   // 10.24 MB
__device__ float g_state1[NSIZE * BATCH];   // 10.24 MB
__device__ float g_bin[NSIZE * BATCH];      // 10.24 MB
__device__ int   g_cnt[NSIZE];
__device__ int   g_off[NSIZE + 1];
__device__ int   g_cur[NSIZE];
__device__ int   g_src[NEDGE];
__device__ float g_w[NEDGE];

// ---------------- CSR construction ----------------

__global__ void zero_cnt_kernel() {
    int i = blockIdx.x * blockDim.x + threadIdx.x;
    if (i < NSIZE) g_cnt[i] = 0;
}

__global__ void hist_kernel(const int* __restrict__ tgt) {
    int e = blockIdx.x * blockDim.x + threadIdx.x;
    if (e < NEDGE) atomicAdd(&g_cnt[tgt[e]], 1);
}

// Single-block exclusive scan over NSIZE counts; also primes g_cur = g_off.
__global__ void scan_kernel() {
    __shared__ int sums[1024];
    const int tid = threadIdx.x;
    const int CH = (NSIZE + 1023) / 1024;   // 20
    const int base = tid * CH;

    int local = 0;
    #pragma unroll
    for (int i = 0; i < CH; i++) {
        int idx = base + i;
        if (idx < NSIZE) local += g_cnt[idx];
    }
    sums[tid] = local;
    __syncthreads();

    // Hillis-Steele inclusive scan
    for (int off = 1; off < 1024; off <<= 1) {
        int v = 0;
        if (tid >= off) v = sums[tid - off];
        __syncthreads();
        if (tid >= off) sums[tid] += v;
        __syncthreads();
    }
    int run = (tid == 0) ? 0 : sums[tid - 1];

    #pragma unroll
    for (int i = 0; i < CH; i++) {
        int idx = base + i;
        if (idx < NSIZE) {
            g_off[idx] = run;
            g_cur[idx] = run;
            run += g_cnt[idx];
        }
    }
    if (tid == 1023) g_off[NSIZE] = run;   // == NEDGE
}

__global__ void scatter_kernel(const int* __restrict__ tgt,
                               const int* __restrict__ srcI,
                               const float* __restrict__ wts) {
    int e = blockIdx.x * blockDim.x + threadIdx.x;
    if (e < NEDGE) {
        int t = tgt[e];
        int pos = atomicAdd(&g_cur[t], 1);
        g_src[pos] = srcI[e];
        g_w[pos]   = wts[e];
    }
}

// ---------------- bIn build (+ first-iteration fold) ----------------
// bIn[t][b] = x[b][t] + bias[t];  state0 = leakyReLU(bIn)  (== xhat after iter 1)

__global__ void binit_kernel(const float* __restrict__ x,
                             const float* __restrict__ bias) {
    __shared__ float tile[32][33];
    int tBase = blockIdx.x * 32;
    int bBase = blockIdx.y * 32;
    // coalesced read of x: lanes vary along t
    int b = bBase + threadIdx.y;
    int t = tBase + threadIdx.x;
    tile[threadIdx.y][threadIdx.x] = x[b * NSIZE + t];
    __syncthreads();
    // coalesced write of bIn: lanes vary along b
    int t2 = tBase + threadIdx.y;
    int b2 = bBase + threadIdx.x;
    float v = tile[threadIdx.x][threadIdx.y] + bias[t2];
    g_bin[t2 * BATCH + b2] = v;
    g_state0[t2 * BATCH + b2] = fmaxf(v, LEAK * v);
}

// ---------------- SpMM iteration: warp per row, float4 per lane ----------------

__global__ void __launch_bounds__(256) spmm_kernel(int flip) {
    const float4* __restrict__ Xin  = (const float4*)(flip ? g_state1 : g_state0);
    float4* __restrict__       Xout = (float4*)(flip ? g_state0 : g_state1);
    const float4* __restrict__ Bin  = (const float4*)g_bin;

    int warp = (blockIdx.x * blockDim.x + threadIdx.x) >> 5;
    int lane = threadIdx.x & 31;
    if (warp >= NSIZE) return;
    int t = warp;

    int beg = g_off[t];
    int end = g_off[t + 1];

    float4 acc = make_float4(0.f, 0.f, 0.f, 0.f);

    int e = beg;
    for (; e + 4 <= end; e += 4) {
        int   s0 = __ldg(&g_src[e + 0]);
        int   s1 = __ldg(&g_src[e + 1]);
        int   s2 = __ldg(&g_src[e + 2]);
        int   s3 = __ldg(&g_src[e + 3]);
        float w0 = __ldg(&g_w[e + 0]);
        float w1 = __ldg(&g_w[e + 1]);
        float w2 = __ldg(&g_w[e + 2]);
        float w3 = __ldg(&g_w[e + 3]);
        float4 v0 = Xin[s0 * 32 + lane];
        float4 v1 = Xin[s1 * 32 + lane];
        float4 v2 = Xin[s2 * 32 + lane];
        float4 v3 = Xin[s3 * 32 + lane];
        acc.x += w0 * v0.x; acc.y += w0 * v0.y; acc.z += w0 * v0.z; acc.w += w0 * v0.w;
        acc.x += w1 * v1.x; acc.y += w1 * v1.y; acc.z += w1 * v1.z; acc.w += w1 * v1.w;
        acc.x += w2 * v2.x; acc.y += w2 * v2.y; acc.z += w2 * v2.z; acc.w += w2 * v2.w;
        acc.x += w3 * v3.x; acc.y += w3 * v3.y; acc.z += w3 * v3.z; acc.w += w3 * v3.w;
    }
    for (; e < end; e++) {
        int   s = __ldg(&g_src[e]);
        float w = __ldg(&g_w[e]);
        float4 v = Xin[s * 32 + lane];
        acc.x += w * v.x; acc.y += w * v.y; acc.z += w * v.z; acc.w += w * v.w;
    }

    float4 b = Bin[t * 32 + lane];
    float4 r;
    r.x = acc.x + b.x; r.y = acc.y + b.y; r.z = acc.z + b.z; r.w = acc.w + b.w;
    r.x = fmaxf(r.x, LEAK * r.x);
    r.y = fmaxf(r.y, LEAK * r.y);
    r.z = fmaxf(r.z, LEAK * r.z);
    r.w = fmaxf(r.w, LEAK * r.w);
    Xout[t * 32 + lane] = r;
}

// ---------------- output transpose: [SIZE,BATCH] -> [BATCH,SIZE] ----------------

__global__ void xpose_kernel(int flip, float* __restrict__ out) {
    const float* __restrict__ st = flip ? g_state1 : g_state0;
    __shared__ float tile[32][33];
    int tBase = blockIdx.x * 32;
    int bBase = blockIdx.y * 32;
    // coalesced read: lanes vary along b
    tile[threadIdx.y][threadIdx.x] = st[(tBase + threadIdx.y) * BATCH + bBase + threadIdx.x];
    __syncthreads();
    // coalesced write: lanes vary along t
    out[(bBase + threadIdx.y) * NSIZE + tBase + threadIdx.x] = tile[threadIdx.x][threadIdx.y];
}

// ---------------- launch ----------------

extern "C" void kernel_launch(void* const* d_in, const int* in_sizes, int n_in,
                              void* d_out, int out_size) {
    const float* x    = (const float*)d_in[0];   // [BATCH, SIZE]
    const float* wts  = (const float*)d_in[1];   // [E]
    const float* bias = (const float*)d_in[2];   // [SIZE]
    const int*   tgt  = (const int*)d_in[3];     // [E]
    const int*   srcI = (const int*)d_in[4];     // [E]
    float* out = (float*)d_out;                  // [BATCH, SIZE]

    // CSR build
    zero_cnt_kernel<<<(NSIZE + 255) / 256, 256>>>();
    hist_kernel<<<(NEDGE + 255) / 256, 256>>>(tgt);
    scan_kernel<<<1, 1024>>>();
    scatter_kernel<<<(NEDGE + 255) / 256, 256>>>(tgt, srcI, wts);

    // bIn + iteration 1 folded in (state0 = act(bIn))
    binit_kernel<<<dim3(NSIZE / 32, BATCH / 32), dim3(32, 32)>>>(x, bias);

    // iterations 2..120  (119 SpMM steps), ping-pong
    const int WARPS_PER_BLOCK = 8;
    const int blocks = (NSIZE + WARPS_PER_BLOCK - 1) / WARPS_PER_BLOCK;  // 2500
    int cur = 0;
    for (int i = 0; i < NITER - 1; i++) {
        spmm_kernel<<<blocks, WARPS_PER_BLOCK * 32>>>(cur);
        cur ^= 1;
    }

    // cur == 1 after 119 steps -> result lives in g_state1
    xpose_kernel<<<dim3(NSIZE / 32, BATCH / 32), dim3(32, 32)>>>(cur, out);
}

// round 2
// speedup vs baseline: 1.1291x; 1.1291x over previous
#include <cuda_runtime.h>
#include <cuda_fp16.h>

#define NSIZE 20000
#define NEDGE 600000
#define BATCH 128
#define NITER 120
#define LEAK  0.01f

#define FP32_TAIL 20                    // last 20 iterations in full fp32
#define FP16_STEPS (NITER - 1 - FP32_TAIL)  // 99 fp16 spmm steps (iters 2..100)

// Scratch: __device__ globals (no allocation allowed).
__device__ float  g_state0[NSIZE * BATCH];   // 10.24 MB (fp32 ping)
__device__ float  g_state1[NSIZE * BATCH];   // 10.24 MB (fp32 pong)
__device__ float  g_bin[NSIZE * BATCH];      // 10.24 MB (fp32 bIn)
__device__ __half g_h0[NSIZE * BATCH];       // 5.12 MB (fp16 ping)
__device__ __half g_h1[NSIZE * BATCH];       // 5.12 MB (fp16 pong)
__device__ __half g_binh[NSIZE * BATCH];     // 5.12 MB (fp16 bIn)
__device__ int    g_cnt[NSIZE];
__device__ int    g_off[NSIZE + 1];
__device__ int    g_cur[NSIZE];
__device__ int    g_src[NEDGE];
__device__ float  g_w[NEDGE];

// ---------------- CSR construction ----------------

__global__ void zero_cnt_kernel() {
    int i = blockIdx.x * blockDim.x + threadIdx.x;
    if (i < NSIZE) g_cnt[i] = 0;
}

__global__ void hist_kernel(const int* __restrict__ tgt) {
    int e = blockIdx.x * blockDim.x + threadIdx.x;
    if (e < NEDGE) atomicAdd(&g_cnt[tgt[e]], 1);
}

__global__ void scan_kernel() {
    __shared__ int sums[1024];
    const int tid = threadIdx.x;
    const int CH = (NSIZE + 1023) / 1024;   // 20
    const int base = tid * CH;

    int local = 0;
    #pragma unroll
    for (int i = 0; i < CH; i++) {
        int idx = base + i;
        if (idx < NSIZE) local += g_cnt[idx];
    }
    sums[tid] = local;
    __syncthreads();

    for (int off = 1; off < 1024; off <<= 1) {
        int v = 0;
        if (tid >= off) v = sums[tid - off];
        __syncthreads();
        if (tid >= off) sums[tid] += v;
        __syncthreads();
    }
    int run = (tid == 0) ? 0 : sums[tid - 1];

    #pragma unroll
    for (int i = 0; i < CH; i++) {
        int idx = base + i;
        if (idx < NSIZE) {
            g_off[idx] = run;
            g_cur[idx] = run;
            run += g_cnt[idx];
        }
    }
    if (tid == 1023) g_off[NSIZE] = run;
}

__global__ void scatter_kernel(const int* __restrict__ tgt,
                               const int* __restrict__ srcI,
                               const float* __restrict__ wts) {
    int e = blockIdx.x * blockDim.x + threadIdx.x;
    if (e < NEDGE) {
        int t = tgt[e];
        int pos = atomicAdd(&g_cur[t], 1);
        g_src[pos] = srcI[e];
        g_w[pos]   = wts[e];
    }
}

// ---------------- bIn build (+ first-iteration fold) ----------------
// bIn[t][b] = x[b][t] + bias[t];  h0 = fp16(leakyReLU(bIn))  (== xhat after iter 1)

__global__ void binit_kernel(const float* __restrict__ x,
                             const float* __restrict__ bias) {
    __shared__ float tile[32][33];
    int tBase = blockIdx.x * 32;
    int bBase = blockIdx.y * 32;
    int b = bBase + threadIdx.y;
    int t = tBase + threadIdx.x;
    tile[threadIdx.y][threadIdx.x] = x[b * NSIZE + t];
    __syncthreads();
    int t2 = tBase + threadIdx.y;
    int b2 = bBase + threadIdx.x;
    float v = tile[threadIdx.x][threadIdx.y] + bias[t2];
    int idx = t2 * BATCH + b2;
    g_bin[idx]  = v;
    g_binh[idx] = __float2half(v);
    g_h0[idx]   = __float2half(fmaxf(v, LEAK * v));
}

// ---------------- fp16-state SpMM: warp per row, 4 batch elems (8B) per lane ----

__global__ void __launch_bounds__(256) spmm_h_kernel(int flip, int writeF32) {
    const uint2* __restrict__ Xin  = (const uint2*)(flip ? g_h1 : g_h0);
    uint2* __restrict__       Xout = (uint2*)(flip ? g_h0 : g_h1);
    const uint2* __restrict__ Binh = (const uint2*)g_binh;

    int warp = (blockIdx.x * blockDim.x + threadIdx.x) >> 5;
    int lane = threadIdx.x & 31;
    if (warp >= NSIZE) return;
    int t = warp;

    int beg = g_off[t];
    int end = g_off[t + 1];

    float4 acc = make_float4(0.f, 0.f, 0.f, 0.f);

    int e = beg;
    for (; e + 4 <= end; e += 4) {
        int   s0 = __ldg(&g_src[e + 0]);
        int   s1 = __ldg(&g_src[e + 1]);
        int   s2 = __ldg(&g_src[e + 2]);
        int   s3 = __ldg(&g_src[e + 3]);
        float w0 = __ldg(&g_w[e + 0]);
        float w1 = __ldg(&g_w[e + 1]);
        float w2 = __ldg(&g_w[e + 2]);
        float w3 = __ldg(&g_w[e + 3]);
        uint2 p0 = Xin[s0 * 32 + lane];
        uint2 p1 = Xin[s1 * 32 + lane];
        uint2 p2 = Xin[s2 * 32 + lane];
        uint2 p3 = Xin[s3 * 32 + lane];
        float2 a0 = __half22float2(*(__half2*)&p0.x), b0 = __half22float2(*(__half2*)&p0.y);
        float2 a1 = __half22float2(*(__half2*)&p1.x), b1 = __half22float2(*(__half2*)&p1.y);
        float2 a2 = __half22float2(*(__half2*)&p2.x), b2 = __half22float2(*(__half2*)&p2.y);
        float2 a3 = __half22float2(*(__half2*)&p3.x), b3 = __half22float2(*(__half2*)&p3.y);
        acc.x += w0 * a0.x; acc.y += w0 * a0.y; acc.z += w0 * b0.x; acc.w += w0 * b0.y;
        acc.x += w1 * a1.x; acc.y += w1 * a1.y; acc.z += w1 * b1.x; acc.w += w1 * b1.y;
        acc.x += w2 * a2.x; acc.y += w2 * a2.y; acc.z += w2 * b2.x; acc.w += w2 * b2.y;
        acc.x += w3 * a3.x; acc.y += w3 * a3.y; acc.z += w3 * b3.x; acc.w += w3 * b3.y;
    }
    for (; e < end; e++) {
        int   s = __ldg(&g_src[e]);
        float w = __ldg(&g_w[e]);
        uint2 p = Xin[s * 32 + lane];
        float2 a = __half22float2(*(__half2*)&p.x), b = __half22float2(*(__half2*)&p.y);
        acc.x += w * a.x; acc.y += w * a.y; acc.z += w * b.x; acc.w += w * b.y;
    }

    uint2 bh = Binh[t * 32 + lane];
    float2 ba = __half22float2(*(__half2*)&bh.x), bb = __half22float2(*(__half2*)&bh.y);
    float4 r;
    r.x = acc.x + ba.x; r.y = acc.y + ba.y; r.z = acc.z + bb.x; r.w = acc.w + bb.y;
    r.x = fmaxf(r.x, LEAK * r.x);
    r.y = fmaxf(r.y, LEAK * r.y);
    r.z = fmaxf(r.z, LEAK * r.z);
    r.w = fmaxf(r.w, LEAK * r.w);

    __half2 h0 = __floats2half2_rn(r.x, r.y);
    __half2 h1 = __floats2half2_rn(r.z, r.w);
    uint2 o; o.x = *(unsigned*)&h0; o.y = *(unsigned*)&h1;
    Xout[t * 32 + lane] = o;

    if (writeF32) {
        // seed the fp32 tail phase (reads g_state0 first)
        ((float4*)g_state0)[t * 32 + lane] = r;
    }
}

// ---------------- fp32 SpMM (tail iterations) ----------------

__global__ void __launch_bounds__(256) spmm_kernel(int flip) {
    const float4* __restrict__ Xin  = (const float4*)(flip ? g_state1 : g_state0);
    float4* __restrict__       Xout = (float4*)(flip ? g_state0 : g_state1);
    const float4* __restrict__ Bin  = (const float4*)g_bin;

    int warp = (blockIdx.x * blockDim.x + threadIdx.x) >> 5;
    int lane = threadIdx.x & 31;
    if (warp >= NSIZE) return;
    int t = warp;

    int beg = g_off[t];
    int end = g_off[t + 1];

    float4 acc = make_float4(0.f, 0.f, 0.f, 0.f);

    int e = beg;
    for (; e + 4 <= end; e += 4) {
        int   s0 = __ldg(&g_src[e + 0]);
        int   s1 = __ldg(&g_src[e + 1]);
        int   s2 = __ldg(&g_src[e + 2]);
        int   s3 = __ldg(&g_src[e + 3]);
        float w0 = __ldg(&g_w[e + 0]);
        float w1 = __ldg(&g_w[e + 1]);
        float w2 = __ldg(&g_w[e + 2]);
        float w3 = __ldg(&g_w[e + 3]);
        float4 v0 = Xin[s0 * 32 + lane];
        float4 v1 = Xin[s1 * 32 + lane];
        float4 v2 = Xin[s2 * 32 + lane];
        float4 v3 = Xin[s3 * 32 + lane];
        acc.x += w0 * v0.x; acc.y += w0 * v0.y; acc.z += w0 * v0.z; acc.w += w0 * v0.w;
        acc.x += w1 * v1.x; acc.y += w1 * v1.y; acc.z += w1 * v1.z; acc.w += w1 * v1.w;
        acc.x += w2 * v2.x; acc.y += w2 * v2.y; acc.z += w2 * v2.z; acc.w += w2 * v2.w;
        acc.x += w3 * v3.x; acc.y += w3 * v3.y; acc.z += w3 * v3.z; acc.w += w3 * v3.w;
    }
    for (; e < end; e++) {
        int   s = __ldg(&g_src[e]);
        float w = __ldg(&g_w[e]);
        float4 v = Xin[s * 32 + lane];
        acc.x += w * v.x; acc.y += w * v.y; acc.z += w * v.z; acc.w += w * v.w;
    }

    float4 b = Bin[t * 32 + lane];
    float4 r;
    r.x = acc.x + b.x; r.y = acc.y + b.y; r.z = acc.z + b.z; r.w = acc.w + b.w;
    r.x = fmaxf(r.x, LEAK * r.x);
    r.y = fmaxf(r.y, LEAK * r.y);
    r.z = fmaxf(r.z, LEAK * r.z);
    r.w = fmaxf(r.w, LEAK * r.w);
    Xout[t * 32 + lane] = r;
}

// ---------------- output transpose: [SIZE,BATCH] -> [BATCH,SIZE] ----------------

__global__ void xpose_kernel(int flip, float* __restrict__ out) {
    const float* __restrict__ st = flip ? g_state1 : g_state0;
    __shared__ float tile[32][33];
    int tBase = blockIdx.x * 32;
    int bBase = blockIdx.y * 32;
    tile[threadIdx.y][threadIdx.x] = st[(tBase + threadIdx.y) * BATCH + bBase + threadIdx.x];
    __syncthreads();
    out[(bBase + threadIdx.y) * NSIZE + tBase + threadIdx.x] = tile[threadIdx.x][threadIdx.y];
}

// ---------------- launch ----------------

extern "C" void kernel_launch(void* const* d_in, const int* in_sizes, int n_in,
                              void* d_out, int out_size) {
    const float* x    = (const float*)d_in[0];   // [BATCH, SIZE]
    const float* wts  = (const float*)d_in[1];   // [E]
    const float* bias = (const float*)d_in[2];   // [SIZE]
    const int*   tgt  = (const int*)d_in[3];     // [E]
    const int*   srcI = (const int*)d_in[4];     // [E]
    float* out = (float*)d_out;                  // [BATCH, SIZE]

    // CSR build
    zero_cnt_kernel<<<(NSIZE + 255) / 256, 256>>>();
    hist_kernel<<<(NEDGE + 255) / 256, 256>>>(tgt);
    scan_kernel<<<1, 1024>>>();
    scatter_kernel<<<(NEDGE + 255) / 256, 256>>>(tgt, srcI, wts);

    // bIn + iteration 1 folded in (h0 = fp16(act(bIn)))
    binit_kernel<<<dim3(NSIZE / 32, BATCH / 32), dim3(32, 32)>>>(x, bias);

    const int WARPS_PER_BLOCK = 8;
    const int blocks = (NSIZE + WARPS_PER_BLOCK - 1) / WARPS_PER_BLOCK;  // 2500

    // fp16 phase: iterations 2 .. 2+FP16_STEPS-1; last step seeds fp32 state0
    int hflip = 0;
    for (int i = 0; i < FP16_STEPS; i++) {
        spmm_h_kernel<<<blocks, WARPS_PER_BLOCK * 32>>>(hflip, (i == FP16_STEPS - 1) ? 1 : 0);
        hflip ^= 1;
    }

    // fp32 tail: FP32_TAIL iterations, starting from g_state0
    int cur = 0;
    for (int i = 0; i < FP32_TAIL; i++) {
        spmm_kernel<<<blocks, WARPS_PER_BLOCK * 32>>>(cur);
        cur ^= 1;
    }

    // FP32_TAIL is even -> cur == 0 -> last write was into g_state0
    xpose_kernel<<<dim3(NSIZE / 32, BATCH / 32), dim3(32, 32)>>>(cur, out);
}